// round 15
// baseline (speedup 1.0000x reference)
#include <cuda_runtime.h>
#include <cuda_bf16.h>
#include <cuda_fp16.h>
#include <math.h>
#include <stdint.h>

#define S_LEN 2048
#define DIN   2048
#define H_Q   32
#define G_KV  8
#define HD    128
#define DOUT  (H_Q*HD)   /* 4096 */
#define GKD   (G_KV*HD)  /* 1024 */
#define QKV_N (DOUT + 2*GKD)  /* 6144 */

// ---------------- scratch (__device__ globals; no runtime alloc) ------------
__device__ __half g_xf16 [S_LEN * (size_t)DIN];
__device__ __half g_cf16 [S_LEN * (size_t)DOUT];
__device__ __half g_wqt [(size_t)DOUT * DIN];
__device__ __half g_wkt [(size_t)GKD  * DIN];
__device__ __half g_wvt [(size_t)GKD  * DIN];
__device__ __half g_wot [(size_t)DIN  * DOUT];

// attention operands (single-rounded fp16)
__device__ __half g_qf [(size_t)H_Q * S_LEN * HD];
__device__ __half g_kh [(size_t)G_KV * S_LEN * HD];
__device__ __half g_vh [(size_t)G_KV * S_LEN * HD];

// ---------------------------- PTX helpers (compute_103-safe) ---------------
__device__ __forceinline__ uint32_t smem_u32(const void* p) {
    uint32_t a;
    asm("{ .reg .u64 t; cvta.to.shared.u64 t, %1; cvt.u32.u64 %0, t; }" : "=r"(a) : "l"(p));
    return a;
}
__device__ __forceinline__ void cp16(uint32_t dst, const void* src) {
    asm volatile("cp.async.cg.shared.global [%0], [%1], 16;\n"
                 :: "r"(dst), "l"(__cvta_generic_to_global(src)));
}
__device__ __forceinline__ void cp_commit() {
    asm volatile("cp.async.commit_group;" ::: "memory");
}
template<int N> __device__ __forceinline__ void cp_wait() {
    asm volatile("cp.async.wait_group %0;" :: "n"(N) : "memory");
}
__device__ __forceinline__ float ex2(float x) {
    float r;
    asm("ex2.approx.f32 %0, %1;" : "=f"(r) : "f"(x));
    return r;
}
#define LDSM4(r, addr) \
    asm volatile("ldmatrix.sync.aligned.m8n8.x4.shared.b16 {%0,%1,%2,%3}, [%4];" \
        : "=r"((r)[0]), "=r"((r)[1]), "=r"((r)[2]), "=r"((r)[3]) : "r"(addr))
#define LDSM4T(r, addr) \
    asm volatile("ldmatrix.sync.aligned.m8n8.x4.trans.shared.b16 {%0,%1,%2,%3}, [%4];" \
        : "=r"((r)[0]), "=r"((r)[1]), "=r"((r)[2]), "=r"((r)[3]) : "r"(addr))
#define MMA_F16(d, a, b0, b1) \
    asm volatile("mma.sync.aligned.m16n8k16.row.col.f32.f16.f16.f32 " \
        "{%0,%1,%2,%3}, {%4,%5,%6,%7}, {%8,%9}, {%0,%1,%2,%3};" \
        : "+f"((d)[0]), "+f"((d)[1]), "+f"((d)[2]), "+f"((d)[3]) \
        : "r"((a)[0]), "r"((a)[1]), "r"((a)[2]), "r"((a)[3]), "r"(b0), "r"(b1))

__device__ __forceinline__ uint32_t pack_f16x2(float lo, float hi) {
    uint32_t r;
    asm("cvt.rn.f16x2.f32 %0, %1, %2;" : "=r"(r) : "f"(hi), "f"(lo));
    return r;
}

// ---------------------------------------------------------------------------
// fp16 single-term GEMM core: CTA 128x128x64, 256 thr, warp tile 64x32,
// 3-stage ring, one sync per stage, loads issued BEFORE compute (max overlap).
// ---------------------------------------------------------------------------
#define TILE_B   18432             /* 128 rows * 144 B */
#define STAGE_B  (2*TILE_B)
#define GEMM_SMEM (3*STAGE_B)      /* 110592 */

#define GEMM_MAINLOOP(Aptr, Bptr, Kdim, m0v)                                        \
    float acc[4][4][4];                                                             \
    _Pragma("unroll")                                                               \
    for (int mi = 0; mi < 4; mi++)                                                  \
        _Pragma("unroll")                                                           \
        for (int ni = 0; ni < 4; ni++)                                              \
            _Pragma("unroll")                                                       \
            for (int q = 0; q < 4; q++) acc[mi][ni][q] = 0.f;                       \
    auto load_stage = [&](int k0, int buf) {                                        \
        uint32_t base = sb + buf * STAGE_B;                                         \
        _Pragma("unroll")                                                           \
        for (int i = 0; i < 8; i++) {                                               \
            int c = tid + (i << 8);                                                 \
            int tile = c >> 10, w = c & 1023, row = w >> 3, ch = w & 7;             \
            const __half* gp;                                                       \
            if (tile == 0) gp = (Aptr) + (size_t)((m0v) + row) * (Kdim) + k0 + (ch << 3); \
            else           gp = (Bptr) + (size_t)row * (Kdim) + k0 + (ch << 3);     \
            cp16(base + tile * TILE_B + row * 144 + (ch << 4), gp);                 \
        }                                                                           \
        cp_commit();                                                                \
    };                                                                              \
    auto compute_stage = [&](int buf) {                                             \
        uint32_t base = sb + buf * STAGE_B;                                         \
        uint32_t sA = base, sB = base + TILE_B;                                     \
        _Pragma("unroll")                                                           \
        for (int kk = 0; kk < 4; kk++) {                                            \
            const int kb = kk * 2;                                                  \
            uint32_t a[4][4], b[2][4];                                              \
            _Pragma("unroll")                                                       \
            for (int mi = 0; mi < 4; mi++) {                                        \
                int row = warp_m * 64 + mi * 16 + (lane & 15);                      \
                LDSM4(a[mi], sA + row * 144 + (kb + (lane >> 4)) * 16);             \
            }                                                                       \
            _Pragma("unroll")                                                       \
            for (int bi = 0; bi < 2; bi++) {                                        \
                int row = warp_n * 32 + bi * 16 + (lane & 7) + ((lane >> 4) << 3);  \
                LDSM4(b[bi], sB + row * 144 + (kb + ((lane >> 3) & 1)) * 16);       \
            }                                                                       \
            _Pragma("unroll")                                                       \
            for (int mi = 0; mi < 4; mi++)                                          \
                _Pragma("unroll")                                                   \
                for (int ni = 0; ni < 4; ni++) {                                    \
                    uint32_t* Bp = &b[ni >> 1][(ni & 1) * 2];                       \
                    MMA_F16(acc[mi][ni], a[mi], Bp[0], Bp[1]);                      \
                }                                                                   \
        }                                                                           \
    };                                                                              \
    const int NS = (Kdim) >> 6;                                                     \
    load_stage(0, 0);                                                               \
    load_stage(64, 1);                                                              \
    for (int t = 0; t < NS; t++) {                                                  \
        if (t + 1 < NS) cp_wait<1>(); else cp_wait<0>();                            \
        __syncthreads();                                                            \
        if (t + 2 < NS) load_stage((t + 2) << 6, (t + 2) % 3);                      \
        compute_stage(t % 3);                                                       \
    }

// ---- merged QKV projection with FUSED RMSNorm+RoPE epilogue ----------------
#define ST_STRIDE 132

__global__ __launch_bounds__(256, 2) void gemm_qkv_kernel(
    const __half* __restrict__ A,
    const __half* __restrict__ Wq16, const __half* __restrict__ Wk16,
    const __half* __restrict__ Wv16,
    const float* __restrict__ qsc, const float* __restrict__ ksc,
    const float* __restrict__ cosp, const float* __restrict__ sinp,
    __half* __restrict__ Qf, float* __restrict__ Kout, __half* __restrict__ Kh,
    float* __restrict__ Cv, __half* __restrict__ Vh)
{
    extern __shared__ __align__(128) char smem[];
    const uint32_t sb = smem_u32(smem);
    const int tid  = threadIdx.x;
    const int wid  = tid >> 5;
    const int lane = tid & 31;
    const int warp_m = wid >> 2;
    const int warp_n = wid & 3;
    const int m0 = blockIdx.y * 128;
    const int n0g = blockIdx.x * 128;

    int seg, nloc;
    const __half* Bp;
    if (n0g < DOUT)            { seg = 0; nloc = n0g;              Bp = Wq16 + (size_t)nloc * DIN; }
    else if (n0g < DOUT + GKD) { seg = 1; nloc = n0g - DOUT;       Bp = Wk16 + (size_t)nloc * DIN; }
    else                       { seg = 2; nloc = n0g - DOUT - GKD; Bp = Wv16 + (size_t)nloc * DIN; }

    GEMM_MAINLOOP(A, Bp, DIN, m0)

    if (seg == 2) {
        #pragma unroll
        for (int mi = 0; mi < 4; mi++) {
            #pragma unroll
            for (int ni = 0; ni < 4; ni++) {
                int r0 = m0 + warp_m * 64 + mi * 16 + (lane >> 2);
                int cl = nloc + warp_n * 32 + ni * 8 + (lane & 3) * 2;
                float2 v01 = make_float2(acc[mi][ni][0], acc[mi][ni][1]);
                float2 v23 = make_float2(acc[mi][ni][2], acc[mi][ni][3]);
                size_t gb = (size_t)(cl >> 7) * S_LEN * HD;
                int cc = cl & 127;
                size_t iA = gb + (size_t)r0 * HD + cc;
                size_t iB = gb + (size_t)(r0 + 8) * HD + cc;
                *(float2*)(Cv + iA) = v01;
                *(float2*)(Cv + iB) = v23;
                ((uint32_t*)Vh)[iA >> 1] = pack_f16x2(v01.x, v01.y);
                ((uint32_t*)Vh)[iB >> 1] = pack_f16x2(v23.x, v23.y);
            }
        }
        return;
    }

    float* st = (float*)smem;
    __syncthreads();
    #pragma unroll
    for (int mi = 0; mi < 4; mi++) {
        #pragma unroll
        for (int ni = 0; ni < 4; ni++) {
            int r0 = warp_m * 64 + mi * 16 + (lane >> 2);
            int c  = warp_n * 32 + ni * 8 + (lane & 3) * 2;
            *(float2*)&st[r0 * ST_STRIDE + c]       = make_float2(acc[mi][ni][0], acc[mi][ni][1]);
            *(float2*)&st[(r0 + 8) * ST_STRIDE + c] = make_float2(acc[mi][ni][2], acc[mi][ni][3]);
        }
    }
    __syncthreads();

    const int head = nloc >> 7;
    const float* scp = (seg == 0) ? qsc : ksc;
    float4 sc = *(const float4*)&scp[lane * 4];
    const float qk_scale = 0.088388347648318447f;

    for (int rr = 0; rr < 16; rr++) {
        int r = wid * 16 + rr;
        int s = m0 + r;
        float4 y = *(float4*)&st[r * ST_STRIDE + lane * 4];
        float ss = y.x * y.x + y.y * y.y + y.z * y.z + y.w * y.w;
        #pragma unroll
        for (int off = 16; off; off >>= 1) ss += __shfl_xor_sync(0xffffffffu, ss, off);
        float inv = rsqrtf(ss * (1.0f / HD) + 1e-6f);
        float y0 = y.x * inv * sc.x, y1 = y.y * inv * sc.y;
        float y2 = y.z * inv * sc.z, y3 = y.w * inv * sc.w;
        float p0 = __shfl_xor_sync(0xffffffffu, y0, 16);
        float p1 = __shfl_xor_sync(0xffffffffu, y1, 16);
        float p2 = __shfl_xor_sync(0xffffffffu, y2, 16);
        float p3 = __shfl_xor_sync(0xffffffffu, y3, 16);
        float sgn = (lane < 16) ? -1.f : 1.f;
        float4 cs = *(const float4*)&cosp[s * HD + lane * 4];
        float4 sn = *(const float4*)&sinp[s * HD + lane * 4];
        float r0 = fmaf(y0, cs.x, sgn * p0 * sn.x);
        float r1 = fmaf(y1, cs.y, sgn * p1 * sn.y);
        float r2 = fmaf(y2, cs.z, sgn * p2 * sn.z);
        float r3 = fmaf(y3, cs.w, sgn * p3 * sn.w);
        size_t o = ((size_t)head * S_LEN + s) * HD + lane * 4;
        if (seg == 0) {
            r0 *= qk_scale; r1 *= qk_scale; r2 *= qk_scale; r3 *= qk_scale;
            ((uint2*)Qf)[o >> 2] = make_uint2(pack_f16x2(r0, r1), pack_f16x2(r2, r3));
        } else {
            *(float4*)&Kout[o] = make_float4(r0, r1, r2, r3);
            ((uint2*)Kh)[o >> 2] = make_uint2(pack_f16x2(r0, r1), pack_f16x2(r2, r3));
        }
    }
}

// ---- Wo GEMM ----
__global__ __launch_bounds__(256, 2) void gemm_wo_kernel(
    const __half* __restrict__ A, const __half* __restrict__ BP,
    float* __restrict__ C, int N, int K)
{
    extern __shared__ __align__(128) char smem[];
    const uint32_t sb = smem_u32(smem);
    const int tid  = threadIdx.x;
    const int wid  = tid >> 5;
    const int lane = tid & 31;
    const int warp_m = wid >> 2;
    const int warp_n = wid & 3;
    const int m0 = blockIdx.y * 128;
    const int n0 = blockIdx.x * 128;
    const __half* Bp = BP + (size_t)n0 * K;

    GEMM_MAINLOOP(A, Bp, K, m0)

    #pragma unroll
    for (int mi = 0; mi < 4; mi++) {
        #pragma unroll
        for (int ni = 0; ni < 4; ni++) {
            int r0 = m0 + warp_m * 64 + mi * 16 + (lane >> 2);
            int c0 = n0 + warp_n * 32 + ni * 8 + (lane & 3) * 2;
            *(float2*)(C + (size_t)r0 * N + c0)       = make_float2(acc[mi][ni][0], acc[mi][ni][1]);
            *(float2*)(C + (size_t)(r0 + 8) * N + c0) = make_float2(acc[mi][ni][2], acc[mi][ni][3]);
        }
    }
}

// ------------------------- combined prep kernel -----------------------------
// blocks [0,4096): x fp32 -> fp16. blocks [4096,24576): weight transposes
// (32x32 tiles) with packed f16x2 writes (16 threads x uint32 per row).
__global__ __launch_bounds__(256) void prep_kernel(
    const float4* __restrict__ xin, ushort4* __restrict__ xf16,
    const float* __restrict__ Wq, const float* __restrict__ Wk,
    const float* __restrict__ Wv, const float* __restrict__ Wo,
    __half* __restrict__ Tq, __half* __restrict__ Tk,
    __half* __restrict__ Tv, __half* __restrict__ To)
{
    __shared__ float t[32][33];
    int bid = blockIdx.x;
    if (bid < 4096) {
        int i = bid * 256 + threadIdx.x;
        float4 v = xin[i];
        xf16[i] = make_ushort4(__half_as_ushort(__float2half_rn(v.x)),
                               __half_as_ushort(__float2half_rn(v.y)),
                               __half_as_ushort(__float2half_rn(v.z)),
                               __half_as_ushort(__float2half_rn(v.w)));
        return;
    }
    bid -= 4096;
    const float* W; __half* T; int K, N, nbx;
    if (bid < 8192)       { W = Wq; T = Tq; K = DIN;  N = DOUT; nbx = 128; }
    else if (bid < 10240) { W = Wk; T = Tk; K = DIN;  N = GKD;  nbx = 32;  bid -= 8192; }
    else if (bid < 12288) { W = Wv; T = Tv; K = DIN;  N = GKD;  nbx = 32;  bid -= 10240; }
    else                  { W = Wo; T = To; K = DOUT; N = DIN;  nbx = 64;  bid -= 12288; }
    const int bn = (bid % nbx) * 32, bk = (bid / nbx) * 32;
    {
        const int tx = threadIdx.x & 31, ty = (threadIdx.x >> 5) * 4;
        #pragma unroll
        for (int j = 0; j < 4; j++)
            t[ty + j][tx] = W[(size_t)(bk + ty + j) * N + bn + tx];
    }
    __syncthreads();
    // packed writes: thread (row i, half-pair hx) writes T[(bn+i)*K + bk + 2hx..2hx+1]
    {
        const int hx = threadIdx.x & 15;          // 0..15 (pairs of k)
        const int i0 = (threadIdx.x >> 4) * 2;    // 0,2,...,30
        #pragma unroll
        for (int j = 0; j < 2; j++) {
            int i = i0 + j;
            uint32_t v = pack_f16x2(t[2*hx][i], t[2*hx+1][i]);
            ((uint32_t*)(T + (size_t)(bn + i) * K + bk))[hx] = v;
        }
    }
}

// ---------------------------------------------------------------------------
// Tensor-core flash attention with static-max softmax (unchanged numerics).
// ---------------------------------------------------------------------------
#define SQA      272
#define Q_BYTES  (128*SQA)
#define KV_TILE  (64*SQA)
#define ATT_SMEM (Q_BYTES + 2*2*KV_TILE)   /* 104448 */
#define EXP_C1   1.4426950408889634f
#define EXP_C2   (-8.0f*1.4426950408889634f + 10.0f)

__global__ __launch_bounds__(256, 2) void attn_mma_kernel(
    const __half* __restrict__ Qf, const __half* __restrict__ Kh,
    const __half* __restrict__ Vh, __half* __restrict__ Cf)
{
    extern __shared__ __align__(128) char smem[];
    const uint32_t sb = smem_u32(smem);
    const int h  = blockIdx.x;
    const int g  = h >> 2;
    const int qt = gridDim.y - 1 - blockIdx.y;
    const int tid = threadIdx.x, wid = tid >> 5, lane = tid & 31;
    const int qbase = qt * 128;

    const uint32_t sQf = sb;
    const uint32_t sKV0 = sb + Q_BYTES;

    {
        const __half* bq = Qf + ((size_t)h * S_LEN + qbase) * HD;
        #pragma unroll
        for (int i = 0; i < 8; i++) {
            int c = tid + (i << 8);
            int r = c >> 4, ch = c & 15;
            cp16(sQf + r * SQA + ch * 16, bq + r * HD + ch * 8);
        }
    }
    auto load_kv = [&](int kt, int buf) {
        uint32_t base = sKV0 + buf * 2 * KV_TILE;
        const size_t gb = ((size_t)g * S_LEN + kt * 64) * HD;
        #pragma unroll
        for (int i = 0; i < 8; i++) {
            int c = tid + (i << 8);
            int arr = c >> 10, w = c & 1023, r = w >> 4, ch = w & 15;
            const __half* src = (arr == 0 ? Kh : Vh) + gb + r * HD + ch * 8;
            cp16(base + arr * KV_TILE + r * SQA + ch * 16, src);
        }
        cp_commit();
    };
    load_kv(0, 0);

    float o[16][4];
    #pragma unroll
    for (int nj = 0; nj < 16; nj++)
        #pragma unroll
        for (int q = 0; q < 4; q++) o[nj][q] = 0.f;
    float lA = 0.f, lB = 0.f;

    const int rA = lane >> 2;
    const int colq = (lane & 3) * 2;
    const int ktmax = 2 * qt + 1;

    for (int kt = 0; kt <= ktmax; kt++) {
        cp_wait<0>();
        __syncthreads();
        if (kt < ktmax) load_kv(kt + 1, (kt + 1) & 1);

        const uint32_t bKh = sKV0 + (kt & 1) * 2 * KV_TILE;
        const uint32_t bVh = bKh + KV_TILE;

        float acc[8][4];
        #pragma unroll
        for (int ni = 0; ni < 8; ni++)
            #pragma unroll
            for (int q = 0; q < 4; q++) acc[ni][q] = 0.f;

        #pragma unroll
        for (int ks = 0; ks < 8; ks++) {
            uint32_t a[4];
            {
                int row = wid * 16 + (lane & 15);
                LDSM4(a, sQf + row * SQA + (ks * 2 + (lane >> 4)) * 16);
            }
            #pragma unroll
            for (int nb = 0; nb < 4; nb++) {
                uint32_t bh[4];
                int row = nb * 16 + (lane & 7) + ((lane >> 4) << 3);
                LDSM4(bh, bKh + row * SQA + (ks * 2 + ((lane >> 3) & 1)) * 16);
                MMA_F16(acc[2*nb],   a, bh[0], bh[1]);
                MMA_F16(acc[2*nb+1], a, bh[2], bh[3]);
            }
        }

        if (kt >= 2 * qt) {
            int qrA = qbase + wid * 16 + rA;
            #pragma unroll
            for (int ni = 0; ni < 8; ni++) {
                int key = kt * 64 + ni * 8 + colq;
                if (key     > qrA)     acc[ni][0] = -1e30f;
                if (key + 1 > qrA)     acc[ni][1] = -1e30f;
                if (key     > qrA + 8) acc[ni][2] = -1e30f;
                if (key + 1 > qrA + 8) acc[ni][3] = -1e30f;
            }
        }

        float sA = 0.f, sB = 0.f;
        #pragma unroll
        for (int ni = 0; ni < 8; ni++) {
            acc[ni][0] = ex2(fmaf(acc[ni][0], EXP_C1, EXP_C2));
            acc[ni][1] = ex2(fmaf(acc[ni][1], EXP_C1, EXP_C2));
            acc[ni][2] = ex2(fmaf(acc[ni][2], EXP_C1, EXP_C2));
            acc[ni][3] = ex2(fmaf(acc[ni][3], EXP_C1, EXP_C2));
            sA += acc[ni][0] + acc[ni][1];
            sB += acc[ni][2] + acc[ni][3];
        }
        lA += sA;
        lB += sB;

        #pragma unroll
        for (int ks = 0; ks < 4; ks++) {
            uint32_t p[4];
            #pragma unroll
            for (int j = 0; j < 4; j++) {
                const float* pr = acc[2 * ks + (j >> 1)];
                p[j] = pack_f16x2(pr[(j & 1) ? 2 : 0], pr[(j & 1) ? 3 : 1]);
            }
            #pragma unroll
            for (int nj = 0; nj < 8; nj++) {
                uint32_t vh[4];
                int row = ks * 16 + (lane & 7) + (((lane >> 3) & 1) << 3);
                LDSM4T(vh, bVh + row * SQA + nj * 32 + (lane >> 4) * 16);
                MMA_F16(o[2*nj],   p, vh[0], vh[1]);
                MMA_F16(o[2*nj+1], p, vh[2], vh[3]);
            }
        }
    }

    float lAt = lA + __shfl_xor_sync(0xffffffffu, lA, 1);
    lAt += __shfl_xor_sync(0xffffffffu, lAt, 2);
    float lBt = lB + __shfl_xor_sync(0xffffffffu, lB, 1);
    lBt += __shfl_xor_sync(0xffffffffu, lBt, 2);
    float invA = 1.f / lAt, invB = 1.f / lBt;

    const int rowA = qbase + wid * 16 + rA;
    uint32_t* C32 = (uint32_t*)Cf;
    #pragma unroll
    for (int nj = 0; nj < 16; nj++) {
        int col = h * HD + nj * 8 + colq;
        float v0 = o[nj][0] * invA, v1 = o[nj][1] * invA;
        float v2 = o[nj][2] * invB, v3 = o[nj][3] * invB;
        C32[(size_t)rowA * (DOUT/2) + (col >> 1)]       = pack_f16x2(v0, v1);
        C32[(size_t)(rowA + 8) * (DOUT/2) + (col >> 1)] = pack_f16x2(v2, v3);
    }
}

// ---------------------------------------------------------------------------
extern "C" void kernel_launch(void* const* d_in, const int* in_sizes, int n_in,
                              void* d_out, int out_size)
{
    const float* x    = (const float*)d_in[0];
    const float* cosp = (const float*)d_in[2];
    const float* sinp = (const float*)d_in[3];
    const float* Wq   = (const float*)d_in[4];
    const float* Wk   = (const float*)d_in[5];
    const float* Wv   = (const float*)d_in[6];
    const float* Wo   = (const float*)d_in[7];
    const float* qsc  = (const float*)d_in[8];
    const float* ksc  = (const float*)d_in[9];

    float* out  = (float*)d_out;
    float* kout = out  + (size_t)S_LEN * DIN;
    float* vout = kout + (size_t)G_KV * S_LEN * HD;

    __half *xf, *cf, *wq16, *wk16, *wv16, *wo16;
    __half *qf, *kh, *vh;
    cudaGetSymbolAddress((void**)&xf,   g_xf16);
    cudaGetSymbolAddress((void**)&cf,   g_cf16);
    cudaGetSymbolAddress((void**)&wq16, g_wqt);
    cudaGetSymbolAddress((void**)&wk16, g_wkt);
    cudaGetSymbolAddress((void**)&wv16, g_wvt);
    cudaGetSymbolAddress((void**)&wo16, g_wot);
    cudaGetSymbolAddress((void**)&qf,   g_qf);
    cudaGetSymbolAddress((void**)&kh,   g_kh);
    cudaGetSymbolAddress((void**)&vh,   g_vh);

    cudaFuncSetAttribute(gemm_qkv_kernel, cudaFuncAttributeMaxDynamicSharedMemorySize, GEMM_SMEM);
    cudaFuncSetAttribute(gemm_wo_kernel,  cudaFuncAttributeMaxDynamicSharedMemorySize, GEMM_SMEM);
    cudaFuncSetAttribute(attn_mma_kernel, cudaFuncAttributeMaxDynamicSharedMemorySize, ATT_SMEM);

    prep_kernel<<<4096 + 20480, 256>>>((const float4*)x, (ushort4*)xf,
                                       Wq, Wk, Wv, Wo, wq16, wk16, wv16, wo16);

    gemm_qkv_kernel<<<dim3(QKV_N/128, S_LEN/128), 256, GEMM_SMEM>>>(
        xf, wq16, wk16, wv16, qsc, ksc, cosp, sinp,
        qf, kout, kh, vout, vh);

    attn_mma_kernel<<<dim3(H_Q, S_LEN/128), 256, ATT_SMEM>>>(qf, kh, vh, cf);

    gemm_wo_kernel<<<dim3(DIN/128, S_LEN/128), 256, GEMM_SMEM>>>(cf, wo16, out, DIN, DOUT);
}

// round 16
// speedup vs baseline: 1.0687x; 1.0687x over previous
#include <cuda_runtime.h>
#include <cuda_bf16.h>
#include <cuda_fp16.h>
#include <math.h>
#include <stdint.h>

#define S_LEN 2048
#define DIN   2048
#define H_Q   32
#define G_KV  8
#define HD    128
#define DOUT  (H_Q*HD)   /* 4096 */
#define GKD   (G_KV*HD)  /* 1024 */
#define QKV_N (DOUT + 2*GKD)  /* 6144 */

// ---------------- scratch (__device__ globals; no runtime alloc) ------------
__device__ __half g_xf16 [S_LEN * (size_t)DIN];
__device__ __half g_cf16 [S_LEN * (size_t)DOUT];
__device__ __half g_wqt [(size_t)DOUT * DIN];
__device__ __half g_wkt [(size_t)GKD  * DIN];
__device__ __half g_wvt [(size_t)GKD  * DIN];
__device__ __half g_wot [(size_t)DIN  * DOUT];

// attention operands (single-rounded fp16)
__device__ __half g_qf [(size_t)H_Q * S_LEN * HD];
__device__ __half g_kh [(size_t)G_KV * S_LEN * HD];
__device__ __half g_vh [(size_t)G_KV * S_LEN * HD];

// ---------------------------- PTX helpers (compute_103-safe) ---------------
__device__ __forceinline__ uint32_t smem_u32(const void* p) {
    uint32_t a;
    asm("{ .reg .u64 t; cvta.to.shared.u64 t, %1; cvt.u32.u64 %0, t; }" : "=r"(a) : "l"(p));
    return a;
}
__device__ __forceinline__ void cp16(uint32_t dst, const void* src) {
    asm volatile("cp.async.cg.shared.global [%0], [%1], 16;\n"
                 :: "r"(dst), "l"(__cvta_generic_to_global(src)));
}
__device__ __forceinline__ void cp_commit() {
    asm volatile("cp.async.commit_group;" ::: "memory");
}
template<int N> __device__ __forceinline__ void cp_wait() {
    asm volatile("cp.async.wait_group %0;" :: "n"(N) : "memory");
}
__device__ __forceinline__ float ex2(float x) {
    float r;
    asm("ex2.approx.f32 %0, %1;" : "=f"(r) : "f"(x));
    return r;
}
#define LDSM4(r, addr) \
    asm volatile("ldmatrix.sync.aligned.m8n8.x4.shared.b16 {%0,%1,%2,%3}, [%4];" \
        : "=r"((r)[0]), "=r"((r)[1]), "=r"((r)[2]), "=r"((r)[3]) : "r"(addr))
#define LDSM4T(r, addr) \
    asm volatile("ldmatrix.sync.aligned.m8n8.x4.trans.shared.b16 {%0,%1,%2,%3}, [%4];" \
        : "=r"((r)[0]), "=r"((r)[1]), "=r"((r)[2]), "=r"((r)[3]) : "r"(addr))
#define MMA_F16(d, a, b0, b1) \
    asm volatile("mma.sync.aligned.m16n8k16.row.col.f32.f16.f16.f32 " \
        "{%0,%1,%2,%3}, {%4,%5,%6,%7}, {%8,%9}, {%0,%1,%2,%3};" \
        : "+f"((d)[0]), "+f"((d)[1]), "+f"((d)[2]), "+f"((d)[3]) \
        : "r"((a)[0]), "r"((a)[1]), "r"((a)[2]), "r"((a)[3]), "r"(b0), "r"(b1))

__device__ __forceinline__ uint32_t pack_f16x2(float lo, float hi) {
    uint32_t r;
    asm("cvt.rn.f16x2.f32 %0, %1, %2;" : "=r"(r) : "f"(hi), "f"(lo));
    return r;
}

// ---------------------------------------------------------------------------
// fp16 single-term GEMM core (R14 ordering restored): CTA 128x128x64, 256 thr,
// warp tile 64x32, 3-stage ring, one sync per stage, compute THEN prefetch.
// ---------------------------------------------------------------------------
#define TILE_B   18432             /* 128 rows * 144 B */
#define STAGE_B  (2*TILE_B)
#define GEMM_SMEM (3*STAGE_B)      /* 110592 */

#define GEMM_MAINLOOP(Aptr, Bptr, Kdim, m0v)                                        \
    float acc[4][4][4];                                                             \
    _Pragma("unroll")                                                               \
    for (int mi = 0; mi < 4; mi++)                                                  \
        _Pragma("unroll")                                                           \
        for (int ni = 0; ni < 4; ni++)                                              \
            _Pragma("unroll")                                                       \
            for (int q = 0; q < 4; q++) acc[mi][ni][q] = 0.f;                       \
    auto load_stage = [&](int k0, int buf) {                                        \
        uint32_t base = sb + buf * STAGE_B;                                         \
        _Pragma("unroll")                                                           \
        for (int i = 0; i < 8; i++) {                                               \
            int c = tid + (i << 8);                                                 \
            int tile = c >> 10, w = c & 1023, row = w >> 3, ch = w & 7;             \
            const __half* gp;                                                       \
            if (tile == 0) gp = (Aptr) + (size_t)((m0v) + row) * (Kdim) + k0 + (ch << 3); \
            else           gp = (Bptr) + (size_t)row * (Kdim) + k0 + (ch << 3);     \
            cp16(base + tile * TILE_B + row * 144 + (ch << 4), gp);                 \
        }                                                                           \
        cp_commit();                                                                \
    };                                                                              \
    auto compute_stage = [&](int buf) {                                             \
        uint32_t base = sb + buf * STAGE_B;                                         \
        uint32_t sA = base, sB = base + TILE_B;                                     \
        _Pragma("unroll")                                                           \
        for (int kk = 0; kk < 4; kk++) {                                            \
            const int kb = kk * 2;                                                  \
            uint32_t a[4][4], b[2][4];                                              \
            _Pragma("unroll")                                                       \
            for (int mi = 0; mi < 4; mi++) {                                        \
                int row = warp_m * 64 + mi * 16 + (lane & 15);                      \
                LDSM4(a[mi], sA + row * 144 + (kb + (lane >> 4)) * 16);             \
            }                                                                       \
            _Pragma("unroll")                                                       \
            for (int bi = 0; bi < 2; bi++) {                                        \
                int row = warp_n * 32 + bi * 16 + (lane & 7) + ((lane >> 4) << 3);  \
                LDSM4(b[bi], sB + row * 144 + (kb + ((lane >> 3) & 1)) * 16);       \
            }                                                                       \
            _Pragma("unroll")                                                       \
            for (int mi = 0; mi < 4; mi++)                                          \
                _Pragma("unroll")                                                   \
                for (int ni = 0; ni < 4; ni++) {                                    \
                    uint32_t* Bp = &b[ni >> 1][(ni & 1) * 2];                       \
                    MMA_F16(acc[mi][ni], a[mi], Bp[0], Bp[1]);                      \
                }                                                                   \
        }                                                                           \
    };                                                                              \
    const int NS = (Kdim) >> 6;                                                     \
    load_stage(0, 0);                                                               \
    load_stage(64, 1);                                                              \
    for (int t = 0; t < NS; t++) {                                                  \
        if (t + 1 < NS) cp_wait<1>(); else cp_wait<0>();                            \
        __syncthreads();                                                            \
        compute_stage(t % 3);                                                       \
        if (t + 2 < NS) load_stage((t + 2) << 6, (t + 2) % 3);                      \
    }

// ---- merged QKV projection with FUSED RMSNorm+RoPE epilogue ----------------
#define ST_STRIDE 132

__global__ __launch_bounds__(256, 2) void gemm_qkv_kernel(
    const __half* __restrict__ A,
    const __half* __restrict__ Wq16, const __half* __restrict__ Wk16,
    const __half* __restrict__ Wv16,
    const float* __restrict__ qsc, const float* __restrict__ ksc,
    const float* __restrict__ cosp, const float* __restrict__ sinp,
    __half* __restrict__ Qf, float* __restrict__ Kout, __half* __restrict__ Kh,
    float* __restrict__ Cv, __half* __restrict__ Vh)
{
    extern __shared__ __align__(128) char smem[];
    const uint32_t sb = smem_u32(smem);
    const int tid  = threadIdx.x;
    const int wid  = tid >> 5;
    const int lane = tid & 31;
    const int warp_m = wid >> 2;
    const int warp_n = wid & 3;
    const int m0 = blockIdx.y * 128;
    const int n0g = blockIdx.x * 128;

    int seg, nloc;
    const __half* Bp;
    if (n0g < DOUT)            { seg = 0; nloc = n0g;              Bp = Wq16 + (size_t)nloc * DIN; }
    else if (n0g < DOUT + GKD) { seg = 1; nloc = n0g - DOUT;       Bp = Wk16 + (size_t)nloc * DIN; }
    else                       { seg = 2; nloc = n0g - DOUT - GKD; Bp = Wv16 + (size_t)nloc * DIN; }

    GEMM_MAINLOOP(A, Bp, DIN, m0)

    if (seg == 2) {
        #pragma unroll
        for (int mi = 0; mi < 4; mi++) {
            #pragma unroll
            for (int ni = 0; ni < 4; ni++) {
                int r0 = m0 + warp_m * 64 + mi * 16 + (lane >> 2);
                int cl = nloc + warp_n * 32 + ni * 8 + (lane & 3) * 2;
                float2 v01 = make_float2(acc[mi][ni][0], acc[mi][ni][1]);
                float2 v23 = make_float2(acc[mi][ni][2], acc[mi][ni][3]);
                size_t gb = (size_t)(cl >> 7) * S_LEN * HD;
                int cc = cl & 127;
                size_t iA = gb + (size_t)r0 * HD + cc;
                size_t iB = gb + (size_t)(r0 + 8) * HD + cc;
                *(float2*)(Cv + iA) = v01;
                *(float2*)(Cv + iB) = v23;
                ((uint32_t*)Vh)[iA >> 1] = pack_f16x2(v01.x, v01.y);
                ((uint32_t*)Vh)[iB >> 1] = pack_f16x2(v23.x, v23.y);
            }
        }
        return;
    }

    float* st = (float*)smem;
    __syncthreads();
    #pragma unroll
    for (int mi = 0; mi < 4; mi++) {
        #pragma unroll
        for (int ni = 0; ni < 4; ni++) {
            int r0 = warp_m * 64 + mi * 16 + (lane >> 2);
            int c  = warp_n * 32 + ni * 8 + (lane & 3) * 2;
            *(float2*)&st[r0 * ST_STRIDE + c]       = make_float2(acc[mi][ni][0], acc[mi][ni][1]);
            *(float2*)&st[(r0 + 8) * ST_STRIDE + c] = make_float2(acc[mi][ni][2], acc[mi][ni][3]);
        }
    }
    __syncthreads();

    const int head = nloc >> 7;
    const float* scp = (seg == 0) ? qsc : ksc;
    float4 sc = *(const float4*)&scp[lane * 4];
    const float qk_scale = 0.088388347648318447f;

    for (int rr = 0; rr < 16; rr++) {
        int r = wid * 16 + rr;
        int s = m0 + r;
        float4 y = *(float4*)&st[r * ST_STRIDE + lane * 4];
        float ss = y.x * y.x + y.y * y.y + y.z * y.z + y.w * y.w;
        #pragma unroll
        for (int off = 16; off; off >>= 1) ss += __shfl_xor_sync(0xffffffffu, ss, off);
        float inv = rsqrtf(ss * (1.0f / HD) + 1e-6f);
        float y0 = y.x * inv * sc.x, y1 = y.y * inv * sc.y;
        float y2 = y.z * inv * sc.z, y3 = y.w * inv * sc.w;
        float p0 = __shfl_xor_sync(0xffffffffu, y0, 16);
        float p1 = __shfl_xor_sync(0xffffffffu, y1, 16);
        float p2 = __shfl_xor_sync(0xffffffffu, y2, 16);
        float p3 = __shfl_xor_sync(0xffffffffu, y3, 16);
        float sgn = (lane < 16) ? -1.f : 1.f;
        float4 cs = *(const float4*)&cosp[s * HD + lane * 4];
        float4 sn = *(const float4*)&sinp[s * HD + lane * 4];
        float r0 = fmaf(y0, cs.x, sgn * p0 * sn.x);
        float r1 = fmaf(y1, cs.y, sgn * p1 * sn.y);
        float r2 = fmaf(y2, cs.z, sgn * p2 * sn.z);
        float r3 = fmaf(y3, cs.w, sgn * p3 * sn.w);
        size_t o = ((size_t)head * S_LEN + s) * HD + lane * 4;
        if (seg == 0) {
            r0 *= qk_scale; r1 *= qk_scale; r2 *= qk_scale; r3 *= qk_scale;
            ((uint2*)Qf)[o >> 2] = make_uint2(pack_f16x2(r0, r1), pack_f16x2(r2, r3));
        } else {
            *(float4*)&Kout[o] = make_float4(r0, r1, r2, r3);
            ((uint2*)Kh)[o >> 2] = make_uint2(pack_f16x2(r0, r1), pack_f16x2(r2, r3));
        }
    }
}

// ---- Wo GEMM ----
__global__ __launch_bounds__(256, 2) void gemm_wo_kernel(
    const __half* __restrict__ A, const __half* __restrict__ BP,
    float* __restrict__ C, int N, int K)
{
    extern __shared__ __align__(128) char smem[];
    const uint32_t sb = smem_u32(smem);
    const int tid  = threadIdx.x;
    const int wid  = tid >> 5;
    const int lane = tid & 31;
    const int warp_m = wid >> 2;
    const int warp_n = wid & 3;
    const int m0 = blockIdx.y * 128;
    const int n0 = blockIdx.x * 128;
    const __half* Bp = BP + (size_t)n0 * K;

    GEMM_MAINLOOP(A, Bp, K, m0)

    #pragma unroll
    for (int mi = 0; mi < 4; mi++) {
        #pragma unroll
        for (int ni = 0; ni < 4; ni++) {
            int r0 = m0 + warp_m * 64 + mi * 16 + (lane >> 2);
            int c0 = n0 + warp_n * 32 + ni * 8 + (lane & 3) * 2;
            *(float2*)(C + (size_t)r0 * N + c0)       = make_float2(acc[mi][ni][0], acc[mi][ni][1]);
            *(float2*)(C + (size_t)(r0 + 8) * N + c0) = make_float2(acc[mi][ni][2], acc[mi][ni][3]);
        }
    }
}

// ------------------------- combined prep kernel -----------------------------
// blocks [0,4096): x fp32 -> fp16. blocks [4096,24576): weight transposes
// (32x32 tiles) with packed f16x2 writes.
__global__ __launch_bounds__(256) void prep_kernel(
    const float4* __restrict__ xin, ushort4* __restrict__ xf16,
    const float* __restrict__ Wq, const float* __restrict__ Wk,
    const float* __restrict__ Wv, const float* __restrict__ Wo,
    __half* __restrict__ Tq, __half* __restrict__ Tk,
    __half* __restrict__ Tv, __half* __restrict__ To)
{
    __shared__ float t[32][33];
    int bid = blockIdx.x;
    if (bid < 4096) {
        int i = bid * 256 + threadIdx.x;
        float4 v = xin[i];
        xf16[i] = make_ushort4(__half_as_ushort(__float2half_rn(v.x)),
                               __half_as_ushort(__float2half_rn(v.y)),
                               __half_as_ushort(__float2half_rn(v.z)),
                               __half_as_ushort(__float2half_rn(v.w)));
        return;
    }
    bid -= 4096;
    const float* W; __half* T; int K, N, nbx;
    if (bid < 8192)       { W = Wq; T = Tq; K = DIN;  N = DOUT; nbx = 128; }
    else if (bid < 10240) { W = Wk; T = Tk; K = DIN;  N = GKD;  nbx = 32;  bid -= 8192; }
    else if (bid < 12288) { W = Wv; T = Tv; K = DIN;  N = GKD;  nbx = 32;  bid -= 10240; }
    else                  { W = Wo; T = To; K = DOUT; N = DIN;  nbx = 64;  bid -= 12288; }
    const int bn = (bid % nbx) * 32, bk = (bid / nbx) * 32;
    {
        const int tx = threadIdx.x & 31, ty = (threadIdx.x >> 5) * 4;
        #pragma unroll
        for (int j = 0; j < 4; j++)
            t[ty + j][tx] = W[(size_t)(bk + ty + j) * N + bn + tx];
    }
    __syncthreads();
    {
        const int hx = threadIdx.x & 15;
        const int i0 = (threadIdx.x >> 4) * 2;
        #pragma unroll
        for (int j = 0; j < 2; j++) {
            int i = i0 + j;
            uint32_t v = pack_f16x2(t[2*hx][i], t[2*hx+1][i]);
            ((uint32_t*)(T + (size_t)(bn + i) * K + bk))[hx] = v;
        }
    }
}

// ---------------------------------------------------------------------------
// Tensor-core flash attention with static-max softmax (R14/R15 numerics).
// ---------------------------------------------------------------------------
#define SQA      272
#define Q_BYTES  (128*SQA)
#define KV_TILE  (64*SQA)
#define ATT_SMEM (Q_BYTES + 2*2*KV_TILE)   /* 104448 */
#define EXP_C1   1.4426950408889634f
#define EXP_C2   (-8.0f*1.4426950408889634f + 10.0f)

__global__ __launch_bounds__(256, 2) void attn_mma_kernel(
    const __half* __restrict__ Qf, const __half* __restrict__ Kh,
    const __half* __restrict__ Vh, __half* __restrict__ Cf)
{
    extern __shared__ __align__(128) char smem[];
    const uint32_t sb = smem_u32(smem);
    const int h  = blockIdx.x;
    const int g  = h >> 2;
    const int qt = gridDim.y - 1 - blockIdx.y;
    const int tid = threadIdx.x, wid = tid >> 5, lane = tid & 31;
    const int qbase = qt * 128;

    const uint32_t sQf = sb;
    const uint32_t sKV0 = sb + Q_BYTES;

    {
        const __half* bq = Qf + ((size_t)h * S_LEN + qbase) * HD;
        #pragma unroll
        for (int i = 0; i < 8; i++) {
            int c = tid + (i << 8);
            int r = c >> 4, ch = c & 15;
            cp16(sQf + r * SQA + ch * 16, bq + r * HD + ch * 8);
        }
    }
    auto load_kv = [&](int kt, int buf) {
        uint32_t base = sKV0 + buf * 2 * KV_TILE;
        const size_t gb = ((size_t)g * S_LEN + kt * 64) * HD;
        #pragma unroll
        for (int i = 0; i < 8; i++) {
            int c = tid + (i << 8);
            int arr = c >> 10, w = c & 1023, r = w >> 4, ch = w & 15;
            const __half* src = (arr == 0 ? Kh : Vh) + gb + r * HD + ch * 8;
            cp16(base + arr * KV_TILE + r * SQA + ch * 16, src);
        }
        cp_commit();
    };
    load_kv(0, 0);

    float o[16][4];
    #pragma unroll
    for (int nj = 0; nj < 16; nj++)
        #pragma unroll
        for (int q = 0; q < 4; q++) o[nj][q] = 0.f;
    float lA = 0.f, lB = 0.f;

    const int rA = lane >> 2;
    const int colq = (lane & 3) * 2;
    const int ktmax = 2 * qt + 1;

    for (int kt = 0; kt <= ktmax; kt++) {
        cp_wait<0>();
        __syncthreads();
        if (kt < ktmax) load_kv(kt + 1, (kt + 1) & 1);

        const uint32_t bKh = sKV0 + (kt & 1) * 2 * KV_TILE;
        const uint32_t bVh = bKh + KV_TILE;

        float acc[8][4];
        #pragma unroll
        for (int ni = 0; ni < 8; ni++)
            #pragma unroll
            for (int q = 0; q < 4; q++) acc[ni][q] = 0.f;

        #pragma unroll
        for (int ks = 0; ks < 8; ks++) {
            uint32_t a[4];
            {
                int row = wid * 16 + (lane & 15);
                LDSM4(a, sQf + row * SQA + (ks * 2 + (lane >> 4)) * 16);
            }
            #pragma unroll
            for (int nb = 0; nb < 4; nb++) {
                uint32_t bh[4];
                int row = nb * 16 + (lane & 7) + ((lane >> 4) << 3);
                LDSM4(bh, bKh + row * SQA + (ks * 2 + ((lane >> 3) & 1)) * 16);
                MMA_F16(acc[2*nb],   a, bh[0], bh[1]);
                MMA_F16(acc[2*nb+1], a, bh[2], bh[3]);
            }
        }

        if (kt >= 2 * qt) {
            int qrA = qbase + wid * 16 + rA;
            #pragma unroll
            for (int ni = 0; ni < 8; ni++) {
                int key = kt * 64 + ni * 8 + colq;
                if (key     > qrA)     acc[ni][0] = -1e30f;
                if (key + 1 > qrA)     acc[ni][1] = -1e30f;
                if (key     > qrA + 8) acc[ni][2] = -1e30f;
                if (key + 1 > qrA + 8) acc[ni][3] = -1e30f;
            }
        }

        float sA = 0.f, sB = 0.f;
        #pragma unroll
        for (int ni = 0; ni < 8; ni++) {
            acc[ni][0] = ex2(fmaf(acc[ni][0], EXP_C1, EXP_C2));
            acc[ni][1] = ex2(fmaf(acc[ni][1], EXP_C1, EXP_C2));
            acc[ni][2] = ex2(fmaf(acc[ni][2], EXP_C1, EXP_C2));
            acc[ni][3] = ex2(fmaf(acc[ni][3], EXP_C1, EXP_C2));
            sA += acc[ni][0] + acc[ni][1];
            sB += acc[ni][2] + acc[ni][3];
        }
        lA += sA;
        lB += sB;

        #pragma unroll
        for (int ks = 0; ks < 4; ks++) {
            uint32_t p[4];
            #pragma unroll
            for (int j = 0; j < 4; j++) {
                const float* pr = acc[2 * ks + (j >> 1)];
                p[j] = pack_f16x2(pr[(j & 1) ? 2 : 0], pr[(j & 1) ? 3 : 1]);
            }
            #pragma unroll
            for (int nj = 0; nj < 8; nj++) {
                uint32_t vh[4];
                int row = ks * 16 + (lane & 7) + (((lane >> 3) & 1) << 3);
                LDSM4T(vh, bVh + row * SQA + nj * 32 + (lane >> 4) * 16);
                MMA_F16(o[2*nj],   p, vh[0], vh[1]);
                MMA_F16(o[2*nj+1], p, vh[2], vh[3]);
            }
        }
    }

    float lAt = lA + __shfl_xor_sync(0xffffffffu, lA, 1);
    lAt += __shfl_xor_sync(0xffffffffu, lAt, 2);
    float lBt = lB + __shfl_xor_sync(0xffffffffu, lB, 1);
    lBt += __shfl_xor_sync(0xffffffffu, lBt, 2);
    float invA = 1.f / lAt, invB = 1.f / lBt;

    const int rowA = qbase + wid * 16 + rA;
    uint32_t* C32 = (uint32_t*)Cf;
    #pragma unroll
    for (int nj = 0; nj < 16; nj++) {
        int col = h * HD + nj * 8 + colq;
        float v0 = o[nj][0] * invA, v1 = o[nj][1] * invA;
        float v2 = o[nj][2] * invB, v3 = o[nj][3] * invB;
        C32[(size_t)rowA * (DOUT/2) + (col >> 1)]       = pack_f16x2(v0, v1);
        C32[(size_t)(rowA + 8) * (DOUT/2) + (col >> 1)] = pack_f16x2(v2, v3);
    }
}

// ---------------------------------------------------------------------------
extern "C" void kernel_launch(void* const* d_in, const int* in_sizes, int n_in,
                              void* d_out, int out_size)
{
    const float* x    = (const float*)d_in[0];
    const float* cosp = (const float*)d_in[2];
    const float* sinp = (const float*)d_in[3];
    const float* Wq   = (const float*)d_in[4];
    const float* Wk   = (const float*)d_in[5];
    const float* Wv   = (const float*)d_in[6];
    const float* Wo   = (const float*)d_in[7];
    const float* qsc  = (const float*)d_in[8];
    const float* ksc  = (const float*)d_in[9];

    float* out  = (float*)d_out;
    float* kout = out  + (size_t)S_LEN * DIN;
    float* vout = kout + (size_t)G_KV * S_LEN * HD;

    __half *xf, *cf, *wq16, *wk16, *wv16, *wo16;
    __half *qf, *kh, *vh;
    cudaGetSymbolAddress((void**)&xf,   g_xf16);
    cudaGetSymbolAddress((void**)&cf,   g_cf16);
    cudaGetSymbolAddress((void**)&wq16, g_wqt);
    cudaGetSymbolAddress((void**)&wk16, g_wkt);
    cudaGetSymbolAddress((void**)&wv16, g_wvt);
    cudaGetSymbolAddress((void**)&wo16, g_wot);
    cudaGetSymbolAddress((void**)&qf,   g_qf);
    cudaGetSymbolAddress((void**)&kh,   g_kh);
    cudaGetSymbolAddress((void**)&vh,   g_vh);

    cudaFuncSetAttribute(gemm_qkv_kernel, cudaFuncAttributeMaxDynamicSharedMemorySize, GEMM_SMEM);
    cudaFuncSetAttribute(gemm_wo_kernel,  cudaFuncAttributeMaxDynamicSharedMemorySize, GEMM_SMEM);
    cudaFuncSetAttribute(attn_mma_kernel, cudaFuncAttributeMaxDynamicSharedMemorySize, ATT_SMEM);

    prep_kernel<<<4096 + 20480, 256>>>((const float4*)x, (ushort4*)xf,
                                       Wq, Wk, Wv, Wo, wq16, wk16, wv16, wo16);

    gemm_qkv_kernel<<<dim3(QKV_N/128, S_LEN/128), 256, GEMM_SMEM>>>(
        xf, wq16, wk16, wv16, qsc, ksc, cosp, sinp,
        qf, kout, kh, vout, vh);

    attn_mma_kernel<<<dim3(H_Q, S_LEN/128), 256, ATT_SMEM>>>(qf, kh, vh, cf);

    gemm_wo_kernel<<<dim3(DIN/128, S_LEN/128), 256, GEMM_SMEM>>>(cf, wo16, out, DIN, DOUT);
}